// round 4
// baseline (speedup 1.0000x reference)
#include <cuda_runtime.h>
#include <math.h>

#define NH   8
#define NQ   2048
#define DH   64
#define CDIM 512
#define NL   64      // landmarks
#define SEG  32      // segment length (2048/64, pad = 0)
#define KL   4       // top-k landmarks

// Scratch (device globals: no allocation allowed in kernel_launch)
__device__ float g_q[NH * NQ * DH];      // (H, N, Dh)
__device__ float g_k[NH * NQ * DH];
__device__ float g_v[NH * NQ * DH];
__device__ float g_cent[NH * NL * DH];   // (H, m, Dh)
__device__ float g_attn[NQ * CDIM];      // (N, H*Dh)  -- pre-projection

// ---------------------------------------------------------------------------
// Tiled fp32 GEMM: C[M,Nc] = A[M,K] @ B[Nc,K]^T  (both row-major, K contiguous)
// MODE 0: A = x, B = w_qkv, epilogue scatters into g_q/g_k/g_v
// MODE 1: A = g_attn, B = w_proj, epilogue adds bias, writes d_out
// Tile: BM=128, BN=64, BK=16, 256 threads, 8x4 per-thread microtile.
// ---------------------------------------------------------------------------
template <int MODE>
__global__ void __launch_bounds__(256) gemm_kernel(
    const float* __restrict__ A, const float* __restrict__ B,
    const float* __restrict__ bias, float* __restrict__ Cout, int Kdim)
{
    constexpr int BM = 128, BN = 64, BK = 16, TM = 8, TN = 4;
    __shared__ float As[BK][BM + 4];
    __shared__ float Bs[BK][BN + 4];

    const float* Aptr = (MODE == 1) ? (const float*)g_attn : A;

    const int tid = threadIdx.x;
    const int bm = blockIdx.y * BM, bn = blockIdx.x * BN;
    const int tx = tid & 15, ty = tid >> 4;

    float acc[TM][TN] = {};

    for (int kt = 0; kt < Kdim; kt += BK) {
        // Load A tile: 128x16 floats = 512 float4, 2 per thread
        #pragma unroll
        for (int i = 0; i < 2; i++) {
            int idx = tid + i * 256;
            int row = idx >> 2, kq = (idx & 3) * 4;
            float4 v = *(const float4*)(Aptr + (size_t)(bm + row) * Kdim + kt + kq);
            As[kq + 0][row] = v.x; As[kq + 1][row] = v.y;
            As[kq + 2][row] = v.z; As[kq + 3][row] = v.w;
        }
        // Load B tile: 64x16 floats = 256 float4, 1 per thread
        {
            int row = tid >> 2, kq = (tid & 3) * 4;
            float4 v = *(const float4*)(B + (size_t)(bn + row) * Kdim + kt + kq);
            Bs[kq + 0][row] = v.x; Bs[kq + 1][row] = v.y;
            Bs[kq + 2][row] = v.z; Bs[kq + 3][row] = v.w;
        }
        __syncthreads();

        #pragma unroll
        for (int kk = 0; kk < BK; kk++) {
            float a[TM], b[TN];
            *(float4*)&a[0] = *(const float4*)&As[kk][ty * TM];
            *(float4*)&a[4] = *(const float4*)&As[kk][ty * TM + 4];
            *(float4*)&b[0] = *(const float4*)&Bs[kk][tx * TN];
            #pragma unroll
            for (int i = 0; i < TM; i++)
                #pragma unroll
                for (int j = 0; j < TN; j++)
                    acc[i][j] += a[i] * b[j];
        }
        __syncthreads();
    }

    if (MODE == 0) {
        // Column block bn spans exactly one (tensor, head) pair since BN == DH
        const int t = bn >> 9;          // 0=q, 1=k, 2=v
        const int h = (bn >> 6) & 7;
        float* dst = (t == 0) ? g_q : (t == 1) ? g_k : g_v;
        #pragma unroll
        for (int i = 0; i < TM; i++) {
            int m = bm + ty * TM + i;
            float4 v = make_float4(acc[i][0], acc[i][1], acc[i][2], acc[i][3]);
            *(float4*)(dst + ((size_t)h * NQ + m) * DH + tx * TN) = v;
        }
    } else {
        float4 bv = *(const float4*)(bias + bn + tx * TN);
        #pragma unroll
        for (int i = 0; i < TM; i++) {
            int m = bm + ty * TM + i;
            float4 v = make_float4(acc[i][0] + bv.x, acc[i][1] + bv.y,
                                   acc[i][2] + bv.z, acc[i][3] + bv.w);
            *(float4*)(Cout + (size_t)m * CDIM + bn + tx * TN) = v;
        }
    }
}

// ---------------------------------------------------------------------------
// Centroids: mean of each 32-row K segment. grid = H*NL blocks x 64 threads.
// ---------------------------------------------------------------------------
__global__ void __launch_bounds__(64) centroid_kernel()
{
    const int hm = blockIdx.x;        // h*NL + m  (NQ = NL*SEG makes this flat)
    const int d = threadIdx.x;
    const float* kp = g_k + (size_t)hm * SEG * DH + d;
    float s = 0.f;
    #pragma unroll
    for (int r = 0; r < SEG; r++) s += kp[r * DH];
    g_cent[(size_t)hm * DH + d] = s * (1.0f / SEG);
}

// ---------------------------------------------------------------------------
// Fused route + top-4 + sparse attention. One warp per (h, n).
// 256 threads = 8 warps per block; grid = H*NQ/8 blocks.
// ---------------------------------------------------------------------------
__global__ void __launch_bounds__(256) attn_kernel()
{
    __shared__ float sq[8][64];    // q vector per warp
    __shared__ float sp[8][128];   // softmax numerators per warp

    const int warp = threadIdx.x >> 5, lane = threadIdx.x & 31;
    const int gw = blockIdx.x * 8 + warp;      // 0 .. H*NQ-1
    const int h = gw >> 11;                    // gw / NQ
    const int n = gw & (NQ - 1);
    const float scale = 0.125f;                // 64^-0.5

    // Stage q into shared (each lane owns dims lane, lane+32)
    const float* qp = g_q + ((size_t)h * NQ + n) * DH;
    float q0 = qp[lane], q1 = qp[lane + 32];
    sq[warp][lane] = q0;
    sq[warp][lane + 32] = q1;
    __syncwarp();

    // Route: lane computes q . centroid for landmarks (lane) and (lane+32)
    const float* cb = g_cent + (size_t)h * NL * DH;
    const float4* c0 = (const float4*)(cb + (size_t)lane * DH);
    const float4* c1 = (const float4*)(cb + (size_t)(lane + 32) * DH);
    float rv0 = 0.f, rv1 = 0.f;
    #pragma unroll
    for (int d4 = 0; d4 < 16; d4++) {
        float4 qv = *(const float4*)&sq[warp][d4 * 4];
        float4 a = c0[d4], b = c1[d4];
        rv0 += qv.x * a.x + qv.y * a.y + qv.z * a.z + qv.w * a.w;
        rv1 += qv.x * b.x + qv.y * b.y + qv.z * b.z + qv.w * b.w;
    }

    // Top-4 (value desc, tie -> lower index, matching jax.lax.top_k)
    int tk[KL];
    #pragma unroll
    for (int t = 0; t < KL; t++) {
        float bv; int bi;
        if (rv0 >= rv1) { bv = rv0; bi = lane; }       // lane < lane+32: tie ok
        else            { bv = rv1; bi = lane + 32; }
        #pragma unroll
        for (int o = 16; o; o >>= 1) {
            float ov = __shfl_xor_sync(0xffffffffu, bv, o);
            int   oi = __shfl_xor_sync(0xffffffffu, bi, o);
            if (ov > bv || (ov == bv && oi < bi)) { bv = ov; bi = oi; }
        }
        tk[t] = bi;
        if (lane == (bi & 31)) {
            if (bi < 32) rv0 = -INFINITY; else rv1 = -INFINITY;
        }
    }

    // Scores over 128 gathered keys: lane handles key (tk[t]*32 + lane), t=0..3
    float sc[KL];
    #pragma unroll
    for (int t = 0; t < KL; t++) {
        const int nk = tk[t] * SEG + lane;
        const float4* kp = (const float4*)(g_k + ((size_t)h * NQ + nk) * DH);
        float s = 0.f;
        #pragma unroll
        for (int d4 = 0; d4 < 16; d4++) {
            float4 qv = *(const float4*)&sq[warp][d4 * 4];
            float4 kv = kp[d4];
            s += qv.x * kv.x + qv.y * kv.y + qv.z * kv.z + qv.w * kv.w;
        }
        sc[t] = s * scale;
    }

    // Softmax over 128 (warp-wide)
    float mx = fmaxf(fmaxf(sc[0], sc[1]), fmaxf(sc[2], sc[3]));
    #pragma unroll
    for (int o = 16; o; o >>= 1) mx = fmaxf(mx, __shfl_xor_sync(0xffffffffu, mx, o));
    float sum = 0.f;
    #pragma unroll
    for (int t = 0; t < KL; t++) { sc[t] = __expf(sc[t] - mx); sum += sc[t]; }
    #pragma unroll
    for (int o = 16; o; o >>= 1) sum += __shfl_xor_sync(0xffffffffu, sum, o);
    const float inv = 1.0f / sum;

    #pragma unroll
    for (int t = 0; t < KL; t++) sp[warp][t * 32 + lane] = sc[t];
    __syncwarp();

    // out[d] = sum_s p[s] * v[key_s][d]; lane owns dims (lane, lane+32)
    float a0 = 0.f, a1 = 0.f;
    #pragma unroll
    for (int t = 0; t < KL; t++) {
        const float* vb = g_v + ((size_t)h * NQ + tk[t] * SEG) * DH;
        #pragma unroll 8
        for (int r = 0; r < SEG; r++) {
            float p = sp[warp][t * 32 + r];
            a0 += p * vb[r * DH + lane];
            a1 += p * vb[r * DH + lane + 32];
        }
    }
    g_attn[(size_t)n * CDIM + h * DH + lane]      = a0 * inv;
    g_attn[(size_t)n * CDIM + h * DH + lane + 32] = a1 * inv;
}

// ---------------------------------------------------------------------------
extern "C" void kernel_launch(void* const* d_in, const int* in_sizes, int n_in,
                              void* d_out, int out_size)
{
    const float* x      = (const float*)d_in[0];   // (1, 2048, 512)
    const float* w_qkv  = (const float*)d_in[1];   // (1536, 512)
    const float* w_proj = (const float*)d_in[2];   // (512, 512)
    const float* b_proj = (const float*)d_in[3];   // (512,)
    float* out = (float*)d_out;                    // (1, 2048, 512)

    // 1) QKV GEMM + scatter to (H,N,Dh) q/k/v
    gemm_kernel<0><<<dim3(3 * CDIM / 64, NQ / 128), 256>>>(x, w_qkv, nullptr, nullptr, CDIM);
    // 2) Landmark centroids
    centroid_kernel<<<NH * NL, 64>>>();
    // 3) Fused route + top-4 + sparse attention
    attn_kernel<<<NH * NQ / 8, 256>>>();
    // 4) Output projection + bias
    gemm_kernel<1><<<dim3(CDIM / 64, NQ / 128), 256>>>(nullptr, w_proj, b_proj, out, CDIM);
}

// round 11
// speedup vs baseline: 1.3084x; 1.3084x over previous
#include <cuda_runtime.h>
#include <cuda_fp16.h>
#include <math.h>
#include <stdint.h>

#define NH   8
#define NQ   2048
#define DH   64
#define CDIM 512
#define NL   64      // landmarks
#define SEG  32      // segment length (2048/64, pad = 0)
#define KL   4       // top-k landmarks

typedef unsigned long long ull;

// Scratch (device globals: no allocation allowed in kernel_launch)
__device__ float g_q[NH * NQ * DH];                    // (H, N, Dh) fp32
__device__ float g_k[NH * NQ * DH];                    // fp32 (centroids only)
__device__ __align__(16) __half g_kh[NH * NQ * DH];    // fp16 copy for scores
__device__ __align__(16) __half g_vh[NH * NQ * DH];    // fp16 V for attention
__device__ float g_cent[NH * NL * DH];                 // (H, m, Dh)
__device__ float g_attn[NQ * CDIM];                    // (N, H*Dh)

// ---------------------------------------------------------------------------
// Packed f32x2 helpers (Blackwell FFMA2 — only reachable via PTX)
// ---------------------------------------------------------------------------
__device__ __forceinline__ ull pack2f(float lo, float hi) {
    ull r; asm("mov.b64 %0, {%1, %2};" : "=l"(r) : "f"(lo), "f"(hi)); return r;
}
__device__ __forceinline__ void unpack2f(ull v, float& lo, float& hi) {
    asm("mov.b64 {%0, %1}, %2;" : "=f"(lo), "=f"(hi) : "l"(v));
}
__device__ __forceinline__ void ffma2(ull& d, ull a, ull b) {
    asm("fma.rn.f32x2 %0, %1, %2, %3;" : "=l"(d) : "l"(a), "l"(b), "l"(d));
}
__device__ __forceinline__ unsigned pk_h2(float a, float b) {
    __half2 h = __float22half2_rn(make_float2(a, b));
    return *(unsigned*)&h;
}

// ===========================================================================
// f32x2 GEMM: C[M,Nc] = A[M,512] @ B[Nc,512]^T  (row-major, K contiguous)
// Tile BM=128, BN=64, BK=16, 256 threads, double-buffered smem.
// Per thread: 4 row-pairs x 4 cols = 16 f32x2 accumulators (8x4 fp32).
// MODE 0: A = x, B = w_qkv; epilogue scatters q/k fp32 + k/v fp16.
// MODE 1: A = g_attn, B = w_proj; epilogue adds bias -> Cout.
// ===========================================================================
template <int MODE>
__global__ void __launch_bounds__(256) gemm_kernel(
    const float* __restrict__ A, const float* __restrict__ B,
    const float* __restrict__ bias, float* __restrict__ Cout)
{
    constexpr int Kd = 512, BK = 16, NK = Kd / BK;
    __shared__ __align__(16) float As[2][BK][128 + 4];
    __shared__ __align__(16) float Bs[2][BK][64 + 4];

    const float* Aptr = (MODE == 1) ? (const float*)g_attn : A;
    const int tid = threadIdx.x;
    const int bm = blockIdx.y * 128, bn = blockIdx.x * 64;
    const int tx = tid & 15, ty = tid >> 4;
    const int lrow = tid >> 2, kq = (tid & 3) * 4;

    const float* Ag0 = Aptr + (size_t)(bm + lrow) * Kd + kq;
    const float* Ag1 = Ag0 + (size_t)64 * Kd;
    const float* Bg  = B + (size_t)(bn + lrow) * Kd + kq;

    ull acc[4][4];
    #pragma unroll
    for (int p = 0; p < 4; p++)
        #pragma unroll
        for (int j = 0; j < 4; j++) acc[p][j] = 0ull;

    float4 ra0, ra1, rb;

#define STORE_TILE(b) do {                                                     \
    As[b][kq+0][lrow]    = ra0.x; As[b][kq+1][lrow]    = ra0.y;                \
    As[b][kq+2][lrow]    = ra0.z; As[b][kq+3][lrow]    = ra0.w;                \
    As[b][kq+0][lrow+64] = ra1.x; As[b][kq+1][lrow+64] = ra1.y;                \
    As[b][kq+2][lrow+64] = ra1.z; As[b][kq+3][lrow+64] = ra1.w;                \
    Bs[b][kq+0][lrow]    = rb.x;  Bs[b][kq+1][lrow]    = rb.y;                 \
    Bs[b][kq+2][lrow]    = rb.z;  Bs[b][kq+3][lrow]    = rb.w;                 \
} while (0)

#define COMP_TILE(b) do {                                                      \
    _Pragma("unroll")                                                          \
    for (int kk = 0; kk < BK; kk++) {                                          \
        const float* Ak = &As[b][kk][ty * 8];                                  \
        ull a01 = *(const ull*)(Ak + 0), a23 = *(const ull*)(Ak + 2);          \
        ull a45 = *(const ull*)(Ak + 4), a67 = *(const ull*)(Ak + 6);          \
        float4 bv = *(const float4*)&Bs[b][kk][tx * 4];                        \
        ull b0 = pack2f(bv.x, bv.x), b1 = pack2f(bv.y, bv.y);                  \
        ull b2 = pack2f(bv.z, bv.z), b3 = pack2f(bv.w, bv.w);                  \
        ffma2(acc[0][0], a01, b0); ffma2(acc[0][1], a01, b1);                  \
        ffma2(acc[0][2], a01, b2); ffma2(acc[0][3], a01, b3);                  \
        ffma2(acc[1][0], a23, b0); ffma2(acc[1][1], a23, b1);                  \
        ffma2(acc[1][2], a23, b2); ffma2(acc[1][3], a23, b3);                  \
        ffma2(acc[2][0], a45, b0); ffma2(acc[2][1], a45, b1);                  \
        ffma2(acc[2][2], a45, b2); ffma2(acc[2][3], a45, b3);                  \
        ffma2(acc[3][0], a67, b0); ffma2(acc[3][1], a67, b1);                  \
        ffma2(acc[3][2], a67, b2); ffma2(acc[3][3], a67, b3);                  \
    }                                                                          \
} while (0)

    ra0 = *(const float4*)Ag0; ra1 = *(const float4*)Ag1; rb = *(const float4*)Bg;
    STORE_TILE(0);
    __syncthreads();

    for (int kt = 0; kt < NK; kt++) {
        const int buf = kt & 1;
        if (kt + 1 < NK) {
            ra0 = *(const float4*)(Ag0 + (kt + 1) * BK);
            ra1 = *(const float4*)(Ag1 + (kt + 1) * BK);
            rb  = *(const float4*)(Bg  + (kt + 1) * BK);
        }
        COMP_TILE(buf);
        if (kt + 1 < NK) {
            STORE_TILE(buf ^ 1);
            __syncthreads();
        }
    }

    // ---- epilogue ----
    if (MODE == 0) {
        const int t = bn >> 9;          // 0=q, 1=k, 2=v   (BN == DH == 64)
        const int h = (bn >> 6) & 7;
        #pragma unroll
        for (int p = 0; p < 4; p++) {
            float lo0, hi0, lo1, hi1, lo2, hi2, lo3, hi3;
            unpack2f(acc[p][0], lo0, hi0); unpack2f(acc[p][1], lo1, hi1);
            unpack2f(acc[p][2], lo2, hi2); unpack2f(acc[p][3], lo3, hi3);
            const int r = bm + ty * 8 + p * 2;
            const size_t rowoff = ((size_t)h * NQ + r) * DH + tx * 4;
            if (t == 0) {
                *(float4*)(g_q + rowoff)      = make_float4(lo0, lo1, lo2, lo3);
                *(float4*)(g_q + rowoff + DH) = make_float4(hi0, hi1, hi2, hi3);
            } else if (t == 1) {
                *(float4*)(g_k + rowoff)      = make_float4(lo0, lo1, lo2, lo3);
                *(float4*)(g_k + rowoff + DH) = make_float4(hi0, hi1, hi2, hi3);
                *(uint2*)(g_kh + rowoff)      = make_uint2(pk_h2(lo0, lo1), pk_h2(lo2, lo3));
                *(uint2*)(g_kh + rowoff + DH) = make_uint2(pk_h2(hi0, hi1), pk_h2(hi2, hi3));
            } else {
                *(uint2*)(g_vh + rowoff)      = make_uint2(pk_h2(lo0, lo1), pk_h2(lo2, lo3));
                *(uint2*)(g_vh + rowoff + DH) = make_uint2(pk_h2(hi0, hi1), pk_h2(hi2, hi3));
            }
        }
    } else {
        float4 bv = *(const float4*)(bias + bn + tx * 4);
        #pragma unroll
        for (int p = 0; p < 4; p++) {
            float lo0, hi0, lo1, hi1, lo2, hi2, lo3, hi3;
            unpack2f(acc[p][0], lo0, hi0); unpack2f(acc[p][1], lo1, hi1);
            unpack2f(acc[p][2], lo2, hi2); unpack2f(acc[p][3], lo3, hi3);
            const int r = bm + ty * 8 + p * 2;
            float* rp = Cout + (size_t)r * CDIM + bn + tx * 4;
            *(float4*)rp = make_float4(lo0 + bv.x, lo1 + bv.y, lo2 + bv.z, lo3 + bv.w);
            *(float4*)(rp + CDIM) = make_float4(hi0 + bv.x, hi1 + bv.y, hi2 + bv.z, hi3 + bv.w);
        }
    }
#undef STORE_TILE
#undef COMP_TILE
}

// ---------------------------------------------------------------------------
// Centroids: mean of each 32-row K segment (fp32 K). grid = H*NL x 64 threads.
// ---------------------------------------------------------------------------
__global__ void __launch_bounds__(64) centroid_kernel()
{
    const int hm = blockIdx.x;        // h*NL + m  (NQ = NL*SEG makes this flat)
    const int d = threadIdx.x;
    const float* kp = g_k + (size_t)hm * SEG * DH + d;
    float s = 0.f;
    #pragma unroll
    for (int r = 0; r < SEG; r++) s += kp[r * DH];
    g_cent[(size_t)hm * DH + d] = s * (1.0f / SEG);
}

// ---------------------------------------------------------------------------
// Fused route + top-4 + sparse attention. One warp per (h, n).
// Routing in fp32 (exact selection); gathered K/V in fp16 (half the L2 bytes).
// ---------------------------------------------------------------------------
__global__ void __launch_bounds__(256) attn_kernel()
{
    __shared__ float sq[8][64];    // q vector per warp
    __shared__ float sp[8][128];   // softmax numerators per warp

    const int warp = threadIdx.x >> 5, lane = threadIdx.x & 31;
    const int gw = blockIdx.x * 8 + warp;      // 0 .. H*NQ-1
    const int h = gw >> 11;                    // gw / NQ
    const int n = gw & (NQ - 1);
    const float scale = 0.125f;                // 64^-0.5

    const float* qp = g_q + ((size_t)h * NQ + n) * DH;
    sq[warp][lane] = qp[lane];
    sq[warp][lane + 32] = qp[lane + 32];
    __syncwarp();

    // Route: lane computes q . centroid for landmarks (lane) and (lane+32)
    const float* cb = g_cent + (size_t)h * NL * DH;
    const float4* c0 = (const float4*)(cb + (size_t)lane * DH);
    const float4* c1 = (const float4*)(cb + (size_t)(lane + 32) * DH);
    float rv0 = 0.f, rv1 = 0.f;
    #pragma unroll
    for (int d4 = 0; d4 < 16; d4++) {
        float4 qv = *(const float4*)&sq[warp][d4 * 4];
        float4 a = c0[d4], b = c1[d4];
        rv0 += qv.x * a.x + qv.y * a.y + qv.z * a.z + qv.w * a.w;
        rv1 += qv.x * b.x + qv.y * b.y + qv.z * b.z + qv.w * b.w;
    }

    // Top-4 (value desc, tie -> lower index, matching jax.lax.top_k)
    int tk[KL];
    #pragma unroll
    for (int t = 0; t < KL; t++) {
        float bv; int bi;
        if (rv0 >= rv1) { bv = rv0; bi = lane; }
        else            { bv = rv1; bi = lane + 32; }
        #pragma unroll
        for (int o = 16; o; o >>= 1) {
            float ov = __shfl_xor_sync(0xffffffffu, bv, o);
            int   oi = __shfl_xor_sync(0xffffffffu, bi, o);
            if (ov > bv || (ov == bv && oi < bi)) { bv = ov; bi = oi; }
        }
        tk[t] = bi;
        if (lane == (bi & 31)) {
            if (bi < 32) rv0 = -INFINITY; else rv1 = -INFINITY;
        }
    }

    // Scores over 128 gathered fp16 keys: lane handles key (tk[t]*32 + lane)
    float sc[KL];
    #pragma unroll
    for (int t = 0; t < KL; t++) {
        const int nk = tk[t] * SEG + lane;
        const uint4* kp = (const uint4*)(g_kh + ((size_t)h * NQ + nk) * DH);
        float s = 0.f;
        #pragma unroll
        for (int i = 0; i < 8; i++) {
            uint4 c = kp[i];
            const float* qb = &sq[warp][i * 8];
            float2 f;
            f = __half22float2(*(__half2*)&c.x); s += qb[0] * f.x + qb[1] * f.y;
            f = __half22float2(*(__half2*)&c.y); s += qb[2] * f.x + qb[3] * f.y;
            f = __half22float2(*(__half2*)&c.z); s += qb[4] * f.x + qb[5] * f.y;
            f = __half22float2(*(__half2*)&c.w); s += qb[6] * f.x + qb[7] * f.y;
        }
        sc[t] = s * scale;
    }

    // Softmax over 128 (warp-wide)
    float mx = fmaxf(fmaxf(sc[0], sc[1]), fmaxf(sc[2], sc[3]));
    #pragma unroll
    for (int o = 16; o; o >>= 1) mx = fmaxf(mx, __shfl_xor_sync(0xffffffffu, mx, o));
    float sum = 0.f;
    #pragma unroll
    for (int t = 0; t < KL; t++) { sc[t] = __expf(sc[t] - mx); sum += sc[t]; }
    #pragma unroll
    for (int o = 16; o; o >>= 1) sum += __shfl_xor_sync(0xffffffffu, sum, o);
    const float inv = 1.0f / sum;

    #pragma unroll
    for (int t = 0; t < KL; t++) sp[warp][t * 32 + lane] = sc[t];
    __syncwarp();

    // out: lane owns dims (2*lane, 2*lane+1) via half2 V rows
    float ax = 0.f, ay = 0.f;
    #pragma unroll
    for (int t = 0; t < KL; t++) {
        const __half2* vb = (const __half2*)(g_vh + ((size_t)h * NQ + tk[t] * SEG) * DH) + lane;
        #pragma unroll 8
        for (int r = 0; r < SEG; r++) {
            float p = sp[warp][t * 32 + r];
            float2 v = __half22float2(vb[r * 32]);
            ax += p * v.x; ay += p * v.y;
        }
    }
    float* op = g_attn + (size_t)n * CDIM + h * DH + 2 * lane;
    *(float2*)op = make_float2(ax * inv, ay * inv);
}

// ---------------------------------------------------------------------------
extern "C" void kernel_launch(void* const* d_in, const int* in_sizes, int n_in,
                              void* d_out, int out_size)
{
    const float* x      = (const float*)d_in[0];   // (1, 2048, 512)
    const float* w_qkv  = (const float*)d_in[1];   // (1536, 512)
    const float* w_proj = (const float*)d_in[2];   // (512, 512)
    const float* b_proj = (const float*)d_in[3];   // (512,)
    float* out = (float*)d_out;                    // (1, 2048, 512)

    // 1) QKV GEMM (f32x2) + scatter q/k fp32, k/v fp16
    gemm_kernel<0><<<dim3(3 * CDIM / 64, NQ / 128), 256>>>(x, w_qkv, nullptr, nullptr);
    // 2) Landmark centroids (fp32)
    centroid_kernel<<<NH * NL, 64>>>();
    // 3) Fused route + top-4 + sparse attention (fp16 K/V gather)
    attn_kernel<<<NH * NQ / 8, 256>>>();
    // 4) Output projection + bias (f32x2)
    gemm_kernel<1><<<dim3(CDIM / 64, NQ / 128), 256>>>(nullptr, w_proj, b_proj, out);
}

// round 12
// speedup vs baseline: 1.4700x; 1.1235x over previous
#include <cuda_runtime.h>
#include <cuda_fp16.h>
#include <math.h>
#include <stdint.h>

#define NH   8
#define NQ   2048
#define DH   64
#define CDIM 512
#define NL   64      // landmarks
#define SEG  32      // segment length (2048/64, pad = 0)
#define KL   4       // top-k landmarks

typedef unsigned long long ull;

// Scratch (device globals: no allocation allowed in kernel_launch)
__device__ float g_q[NH * NQ * DH];                    // (H, N, Dh) fp32
__device__ float g_k[NH * NQ * DH];                    // fp32 (centroids only)
__device__ __align__(16) __half g_kh[NH * NQ * DH];    // fp16 K for scores
__device__ __align__(16) __half g_vh[NH * NQ * DH];    // fp16 V for attention
__device__ float g_cent[NH * NL * DH];                 // (H, m, Dh)
__device__ float g_attn[NQ * CDIM];                    // (N, H*Dh)

// Inverted-gather structures
__device__ int   g_cnt[NH * NL];                       // routed-query counts
__device__ int   g_list[NH * NL * NQ];                 // packed (n | t<<16)
__device__ float g_pm[NH * NQ * KL];                   // per-(q,rank) max
__device__ float g_pl[NH * NQ * KL];                   // per-(q,rank) sumexp
__device__ float g_po[NH * NQ * KL * DH];              // per-(q,rank) partial out

// ---------------------------------------------------------------------------
// Packed f32x2 helpers (Blackwell FFMA2 — only reachable via PTX)
// ---------------------------------------------------------------------------
__device__ __forceinline__ ull pack2f(float lo, float hi) {
    ull r; asm("mov.b64 %0, {%1, %2};" : "=l"(r) : "f"(lo), "f"(hi)); return r;
}
__device__ __forceinline__ void unpack2f(ull v, float& lo, float& hi) {
    asm("mov.b64 {%0, %1}, %2;" : "=f"(lo), "=f"(hi) : "l"(v));
}
__device__ __forceinline__ void ffma2(ull& d, ull a, ull b) {
    asm("fma.rn.f32x2 %0, %1, %2, %3;" : "=l"(d) : "l"(a), "l"(b), "l"(d));
}
__device__ __forceinline__ unsigned pk_h2(float a, float b) {
    __half2 h = __float22half2_rn(make_float2(a, b));
    return *(unsigned*)&h;
}

// ===========================================================================
// f32x2 GEMM (unchanged from R11): C[M,Nc] = A[M,512] @ B[Nc,512]^T
// ===========================================================================
template <int MODE>
__global__ void __launch_bounds__(256) gemm_kernel(
    const float* __restrict__ A, const float* __restrict__ B,
    const float* __restrict__ bias, float* __restrict__ Cout)
{
    constexpr int Kd = 512, BK = 16, NK = Kd / BK;
    __shared__ __align__(16) float As[2][BK][128 + 4];
    __shared__ __align__(16) float Bs[2][BK][64 + 4];

    const float* Aptr = (MODE == 1) ? (const float*)g_attn : A;
    const int tid = threadIdx.x;
    const int bm = blockIdx.y * 128, bn = blockIdx.x * 64;
    const int tx = tid & 15, ty = tid >> 4;
    const int lrow = tid >> 2, kq = (tid & 3) * 4;

    const float* Ag0 = Aptr + (size_t)(bm + lrow) * Kd + kq;
    const float* Ag1 = Ag0 + (size_t)64 * Kd;
    const float* Bg  = B + (size_t)(bn + lrow) * Kd + kq;

    ull acc[4][4];
    #pragma unroll
    for (int p = 0; p < 4; p++)
        #pragma unroll
        for (int j = 0; j < 4; j++) acc[p][j] = 0ull;

    float4 ra0, ra1, rb;

#define STORE_TILE(b) do {                                                     \
    As[b][kq+0][lrow]    = ra0.x; As[b][kq+1][lrow]    = ra0.y;                \
    As[b][kq+2][lrow]    = ra0.z; As[b][kq+3][lrow]    = ra0.w;                \
    As[b][kq+0][lrow+64] = ra1.x; As[b][kq+1][lrow+64] = ra1.y;                \
    As[b][kq+2][lrow+64] = ra1.z; As[b][kq+3][lrow+64] = ra1.w;                \
    Bs[b][kq+0][lrow]    = rb.x;  Bs[b][kq+1][lrow]    = rb.y;                 \
    Bs[b][kq+2][lrow]    = rb.z;  Bs[b][kq+3][lrow]    = rb.w;                 \
} while (0)

#define COMP_TILE(b) do {                                                      \
    _Pragma("unroll")                                                          \
    for (int kk = 0; kk < BK; kk++) {                                          \
        const float* Ak = &As[b][kk][ty * 8];                                  \
        ull a01 = *(const ull*)(Ak + 0), a23 = *(const ull*)(Ak + 2);          \
        ull a45 = *(const ull*)(Ak + 4), a67 = *(const ull*)(Ak + 6);          \
        float4 bv = *(const float4*)&Bs[b][kk][tx * 4];                        \
        ull b0 = pack2f(bv.x, bv.x), b1 = pack2f(bv.y, bv.y);                  \
        ull b2 = pack2f(bv.z, bv.z), b3 = pack2f(bv.w, bv.w);                  \
        ffma2(acc[0][0], a01, b0); ffma2(acc[0][1], a01, b1);                  \
        ffma2(acc[0][2], a01, b2); ffma2(acc[0][3], a01, b3);                  \
        ffma2(acc[1][0], a23, b0); ffma2(acc[1][1], a23, b1);                  \
        ffma2(acc[1][2], a23, b2); ffma2(acc[1][3], a23, b3);                  \
        ffma2(acc[2][0], a45, b0); ffma2(acc[2][1], a45, b1);                  \
        ffma2(acc[2][2], a45, b2); ffma2(acc[2][3], a45, b3);                  \
        ffma2(acc[3][0], a67, b0); ffma2(acc[3][1], a67, b1);                  \
        ffma2(acc[3][2], a67, b2); ffma2(acc[3][3], a67, b3);                  \
    }                                                                          \
} while (0)

    ra0 = *(const float4*)Ag0; ra1 = *(const float4*)Ag1; rb = *(const float4*)Bg;
    STORE_TILE(0);
    __syncthreads();

    for (int kt = 0; kt < NK; kt++) {
        const int buf = kt & 1;
        if (kt + 1 < NK) {
            ra0 = *(const float4*)(Ag0 + (kt + 1) * BK);
            ra1 = *(const float4*)(Ag1 + (kt + 1) * BK);
            rb  = *(const float4*)(Bg  + (kt + 1) * BK);
        }
        COMP_TILE(buf);
        if (kt + 1 < NK) {
            STORE_TILE(buf ^ 1);
            __syncthreads();
        }
    }

    if (MODE == 0) {
        const int t = bn >> 9;          // 0=q, 1=k, 2=v   (BN == DH == 64)
        const int h = (bn >> 6) & 7;
        #pragma unroll
        for (int p = 0; p < 4; p++) {
            float lo0, hi0, lo1, hi1, lo2, hi2, lo3, hi3;
            unpack2f(acc[p][0], lo0, hi0); unpack2f(acc[p][1], lo1, hi1);
            unpack2f(acc[p][2], lo2, hi2); unpack2f(acc[p][3], lo3, hi3);
            const int r = bm + ty * 8 + p * 2;
            const size_t rowoff = ((size_t)h * NQ + r) * DH + tx * 4;
            if (t == 0) {
                *(float4*)(g_q + rowoff)      = make_float4(lo0, lo1, lo2, lo3);
                *(float4*)(g_q + rowoff + DH) = make_float4(hi0, hi1, hi2, hi3);
            } else if (t == 1) {
                *(float4*)(g_k + rowoff)      = make_float4(lo0, lo1, lo2, lo3);
                *(float4*)(g_k + rowoff + DH) = make_float4(hi0, hi1, hi2, hi3);
                *(uint2*)(g_kh + rowoff)      = make_uint2(pk_h2(lo0, lo1), pk_h2(lo2, lo3));
                *(uint2*)(g_kh + rowoff + DH) = make_uint2(pk_h2(hi0, hi1), pk_h2(hi2, hi3));
            } else {
                *(uint2*)(g_vh + rowoff)      = make_uint2(pk_h2(lo0, lo1), pk_h2(lo2, lo3));
                *(uint2*)(g_vh + rowoff + DH) = make_uint2(pk_h2(hi0, hi1), pk_h2(hi2, hi3));
            }
        }
    } else {
        float4 bv = *(const float4*)(bias + bn + tx * 4);
        #pragma unroll
        for (int p = 0; p < 4; p++) {
            float lo0, hi0, lo1, hi1, lo2, hi2, lo3, hi3;
            unpack2f(acc[p][0], lo0, hi0); unpack2f(acc[p][1], lo1, hi1);
            unpack2f(acc[p][2], lo2, hi2); unpack2f(acc[p][3], lo3, hi3);
            const int r = bm + ty * 8 + p * 2;
            float* rp = Cout + (size_t)r * CDIM + bn + tx * 4;
            *(float4*)rp = make_float4(lo0 + bv.x, lo1 + bv.y, lo2 + bv.z, lo3 + bv.w);
            *(float4*)(rp + CDIM) = make_float4(hi0 + bv.x, hi1 + bv.y, hi2 + bv.z, hi3 + bv.w);
        }
    }
#undef STORE_TILE
#undef COMP_TILE
}

// ---------------------------------------------------------------------------
// Centroids: mean of each 32-row K segment (fp32 K).
// ---------------------------------------------------------------------------
__global__ void __launch_bounds__(64) centroid_kernel()
{
    const int hm = blockIdx.x;
    const int d = threadIdx.x;
    const float* kp = g_k + (size_t)hm * SEG * DH + d;
    float s = 0.f;
    #pragma unroll
    for (int r = 0; r < SEG; r++) s += kp[r * DH];
    g_cent[(size_t)hm * DH + d] = s * (1.0f / SEG);
}

// ---------------------------------------------------------------------------
// Zero the routing counters (runs every replay — graph determinism).
// ---------------------------------------------------------------------------
__global__ void __launch_bounds__(512) zero_kernel()
{
    g_cnt[threadIdx.x] = 0;
}

// ---------------------------------------------------------------------------
// Routing: fp32 route + top-4 per (h,n); append (n | t<<16) to landmark lists.
// One warp per (h,n). Selection identical to R11 (jax tie-break: lower index).
// ---------------------------------------------------------------------------
__global__ void __launch_bounds__(256) route_kernel()
{
    __shared__ float sq[8][64];

    const int warp = threadIdx.x >> 5, lane = threadIdx.x & 31;
    const int gw = blockIdx.x * 8 + warp;
    const int h = gw >> 11;
    const int n = gw & (NQ - 1);

    const float* qp = g_q + ((size_t)h * NQ + n) * DH;
    sq[warp][lane] = qp[lane];
    sq[warp][lane + 32] = qp[lane + 32];
    __syncwarp();

    const float* cb = g_cent + (size_t)h * NL * DH;
    const float4* c0 = (const float4*)(cb + (size_t)lane * DH);
    const float4* c1 = (const float4*)(cb + (size_t)(lane + 32) * DH);
    float rv0 = 0.f, rv1 = 0.f;
    #pragma unroll
    for (int d4 = 0; d4 < 16; d4++) {
        float4 qv = *(const float4*)&sq[warp][d4 * 4];
        float4 a = c0[d4], b = c1[d4];
        rv0 += qv.x * a.x + qv.y * a.y + qv.z * a.z + qv.w * a.w;
        rv1 += qv.x * b.x + qv.y * b.y + qv.z * b.z + qv.w * b.w;
    }

    int tk[KL];
    #pragma unroll
    for (int t = 0; t < KL; t++) {
        float bv; int bi;
        if (rv0 >= rv1) { bv = rv0; bi = lane; }
        else            { bv = rv1; bi = lane + 32; }
        #pragma unroll
        for (int o = 16; o; o >>= 1) {
            float ov = __shfl_xor_sync(0xffffffffu, bv, o);
            int   oi = __shfl_xor_sync(0xffffffffu, bi, o);
            if (ov > bv || (ov == bv && oi < bi)) { bv = ov; bi = oi; }
        }
        tk[t] = bi;
        if (lane == (bi & 31)) {
            if (bi < 32) rv0 = -INFINITY; else rv1 = -INFINITY;
        }
    }

    // lanes 0..3 append (n, rank) to their landmark's list
    if (lane < KL) {
        const int hm = h * NL + tk[lane];
        const int slot = atomicAdd(&g_cnt[hm], 1);
        g_list[(size_t)hm * NQ + slot] = n | (lane << 16);
    }
}

// ---------------------------------------------------------------------------
// Phase A: one block per (h, landmark). K/V segment staged in smem once;
// each warp holds key row `lane` in registers and streams routed queries,
// writing flash-style partials (m, l, o[64]) indexed by (h, n, rank).
// ---------------------------------------------------------------------------
__global__ void __launch_bounds__(256) seg_attn_kernel()
{
    __shared__ __half ks[SEG][DH + 2];   // +2 halves: 132B row stride (bank-safe)
    __shared__ __half2 vs[SEG][DH / 2];  // natural layout: conflict-free by lane
    __shared__ float sq[8][64];
    __shared__ float sp[8][SEG];
    __shared__ int s_cnt;

    const int tid = threadIdx.x, warp = tid >> 5, lane = tid & 31;
    const int hm = blockIdx.x;           // h*NL + m
    const int h = hm >> 6;
    const float scale = 0.125f;

    const size_t seg_base = (size_t)hm * SEG * DH;   // == (h*NQ + m*SEG)*DH
    // cooperative tile load (coalesced global reads)
    for (int i = tid; i < SEG * DH; i += 256) {
        int r = i >> 6, c = i & 63;
        ks[r][c] = g_kh[seg_base + i];
        ((__half*)&vs[r][0])[c] = g_vh[seg_base + i];
    }
    if (tid == 0) s_cnt = g_cnt[hm];
    __syncthreads();

    // each lane caches its key row (32 half2 regs)
    __half2 kreg[DH / 2];
    #pragma unroll
    for (int c = 0; c < DH / 2; c++)
        kreg[c] = *(const __half2*)&ks[lane][2 * c];

    const int cnt = s_cnt;
    const int* list = g_list + (size_t)hm * NQ;

    for (int i = warp; i < cnt; i += 8) {
        const int e = list[i];
        const int n = e & 0xffff, t = e >> 16;

        const float* qp = g_q + ((size_t)h * NQ + n) * DH;
        sq[warp][lane] = qp[lane];
        sq[warp][lane + 32] = qp[lane + 32];
        __syncwarp();

        // score for key `lane`
        float s = 0.f;
        #pragma unroll
        for (int c = 0; c < DH / 2; c++) {
            float2 kf = __half22float2(kreg[c]);
            s += sq[warp][2 * c] * kf.x + sq[warp][2 * c + 1] * kf.y;
        }
        s *= scale;

        // segment-local softmax partials
        float mx = s;
        #pragma unroll
        for (int o = 16; o; o >>= 1) mx = fmaxf(mx, __shfl_xor_sync(0xffffffffu, mx, o));
        float p = __expf(s - mx);
        float l = p;
        #pragma unroll
        for (int o = 16; o; o >>= 1) l += __shfl_xor_sync(0xffffffffu, l, o);

        sp[warp][lane] = p;
        __syncwarp();

        // o[d] = sum_j p_j * V[j][d]; lane owns dims (2*lane, 2*lane+1)
        float ax = 0.f, ay = 0.f;
        #pragma unroll
        for (int j = 0; j < SEG; j++) {
            float pj = sp[warp][j];
            float2 v = __half22float2(vs[j][lane]);
            ax += pj * v.x; ay += pj * v.y;
        }

        const size_t pb = ((size_t)h * NQ + n) * KL + t;
        *(float2*)(g_po + pb * DH + 2 * lane) = make_float2(ax, ay);
        if (lane == 0) { g_pm[pb] = mx; g_pl[pb] = l; }
        __syncwarp();
    }
}

// ---------------------------------------------------------------------------
// Combine: merge the 4 rank partials per query (exact two-level softmax).
// One warp per (h,n).
// ---------------------------------------------------------------------------
__global__ void __launch_bounds__(256) combine_kernel()
{
    const int warp = threadIdx.x >> 5, lane = threadIdx.x & 31;
    const int gw = blockIdx.x * 8 + warp;
    const int h = gw >> 11;
    const int n = gw & (NQ - 1);

    const size_t pb = ((size_t)h * NQ + n) * KL;

    float m0 = g_pm[pb + 0], m1 = g_pm[pb + 1], m2 = g_pm[pb + 2], m3 = g_pm[pb + 3];
    float l0 = g_pl[pb + 0], l1 = g_pl[pb + 1], l2 = g_pl[pb + 2], l3 = g_pl[pb + 3];
    const float M = fmaxf(fmaxf(m0, m1), fmaxf(m2, m3));
    const float w0 = __expf(m0 - M), w1 = __expf(m1 - M);
    const float w2 = __expf(m2 - M), w3 = __expf(m3 - M);
    const float inv = 1.0f / (l0 * w0 + l1 * w1 + l2 * w2 + l3 * w3);

    float2 o0 = *(const float2*)(g_po + (pb + 0) * DH + 2 * lane);
    float2 o1 = *(const float2*)(g_po + (pb + 1) * DH + 2 * lane);
    float2 o2 = *(const float2*)(g_po + (pb + 2) * DH + 2 * lane);
    float2 o3 = *(const float2*)(g_po + (pb + 3) * DH + 2 * lane);

    float ax = w0 * o0.x + w1 * o1.x + w2 * o2.x + w3 * o3.x;
    float ay = w0 * o0.y + w1 * o1.y + w2 * o2.y + w3 * o3.y;

    float* op = g_attn + (size_t)n * CDIM + h * DH + 2 * lane;
    *(float2*)op = make_float2(ax * inv, ay * inv);
}

// ---------------------------------------------------------------------------
extern "C" void kernel_launch(void* const* d_in, const int* in_sizes, int n_in,
                              void* d_out, int out_size)
{
    const float* x      = (const float*)d_in[0];   // (1, 2048, 512)
    const float* w_qkv  = (const float*)d_in[1];   // (1536, 512)
    const float* w_proj = (const float*)d_in[2];   // (512, 512)
    const float* b_proj = (const float*)d_in[3];   // (512,)
    float* out = (float*)d_out;                    // (1, 2048, 512)

    // 1) QKV GEMM (f32x2) + scatter q/k fp32, k/v fp16
    gemm_kernel<0><<<dim3(3 * CDIM / 64, NQ / 128), 256>>>(x, w_qkv, nullptr, nullptr);
    // 2) Landmark centroids (fp32)
    centroid_kernel<<<NH * NL, 64>>>();
    // 3) Routing: top-4 landmarks per query + inverted lists
    zero_kernel<<<1, 512>>>();
    route_kernel<<<NH * NQ / 8, 256>>>();
    // 4) Phase A: per-(h,landmark) segment attention -> partials
    seg_attn_kernel<<<NH * NL, 256>>>();
    // 5) Combine partials (exact softmax merge)
    combine_kernel<<<NH * NQ / 8, 256>>>();
    // 6) Output projection + bias (f32x2)
    gemm_kernel<1><<<dim3(CDIM / 64, NQ / 128), 256>>>(nullptr, w_proj, b_proj, out);
}

// round 13
// speedup vs baseline: 1.6730x; 1.1381x over previous
#include <cuda_runtime.h>
#include <cuda_fp16.h>
#include <math.h>
#include <stdint.h>

#define NH   8
#define NQ   2048
#define DH   64
#define CDIM 512
#define NL   64      // landmarks
#define SEG  32      // segment length (2048/64, pad = 0)
#define KL   4       // top-k landmarks

typedef unsigned long long ull;

// Scratch (device globals: no allocation allowed in kernel_launch)
__device__ float g_q[NH * NQ * DH];                    // (H, N, Dh) fp32
__device__ float g_k[NH * NQ * DH];                    // fp32 (centroids only)
__device__ __align__(16) __half g_kh[NH * NQ * DH];    // fp16 K for scores
__device__ __align__(16) __half g_vh[NH * NQ * DH];    // fp16 V for attention
__device__ float g_cent[NH * NL * DH];                 // (H, m, Dh)
__device__ float g_attn[NQ * CDIM];                    // (N, H*Dh)

// Inverted-gather structures
__device__ int   g_cnt[NH * NL];                       // routed-query counts
__device__ int   g_list[NH * NL * NQ];                 // packed (n | t<<16)
__device__ float g_pm[NH * NQ * KL];                   // per-(q,rank) max
__device__ float g_pl[NH * NQ * KL];                   // per-(q,rank) sumexp
__device__ float g_po[NH * NQ * KL * DH];              // per-(q,rank) partial out

// ---------------------------------------------------------------------------
// Packed f32x2 helpers (Blackwell FFMA2 — only reachable via PTX)
// ---------------------------------------------------------------------------
__device__ __forceinline__ ull pack2f(float lo, float hi) {
    ull r; asm("mov.b64 %0, {%1, %2};" : "=l"(r) : "f"(lo), "f"(hi)); return r;
}
__device__ __forceinline__ void unpack2f(ull v, float& lo, float& hi) {
    asm("mov.b64 {%0, %1}, %2;" : "=f"(lo), "=f"(hi) : "l"(v));
}
__device__ __forceinline__ void ffma2(ull& d, ull a, ull b) {
    asm("fma.rn.f32x2 %0, %1, %2, %3;" : "=l"(d) : "l"(a), "l"(b), "l"(d));
}
__device__ __forceinline__ unsigned pk_h2(float a, float b) {
    __half2 h = __float22half2_rn(make_float2(a, b));
    return *(unsigned*)&h;
}

// ===========================================================================
// f32x2 GEMM (unchanged from R12): C[M,Nc] = A[M,512] @ B[Nc,512]^T
// ===========================================================================
template <int MODE>
__global__ void __launch_bounds__(256) gemm_kernel(
    const float* __restrict__ A, const float* __restrict__ B,
    const float* __restrict__ bias, float* __restrict__ Cout)
{
    constexpr int Kd = 512, BK = 16, NK = Kd / BK;
    __shared__ __align__(16) float As[2][BK][128 + 4];
    __shared__ __align__(16) float Bs[2][BK][64 + 4];

    const float* Aptr = (MODE == 1) ? (const float*)g_attn : A;
    const int tid = threadIdx.x;
    const int bm = blockIdx.y * 128, bn = blockIdx.x * 64;
    const int tx = tid & 15, ty = tid >> 4;
    const int lrow = tid >> 2, kq = (tid & 3) * 4;

    const float* Ag0 = Aptr + (size_t)(bm + lrow) * Kd + kq;
    const float* Ag1 = Ag0 + (size_t)64 * Kd;
    const float* Bg  = B + (size_t)(bn + lrow) * Kd + kq;

    ull acc[4][4];
    #pragma unroll
    for (int p = 0; p < 4; p++)
        #pragma unroll
        for (int j = 0; j < 4; j++) acc[p][j] = 0ull;

    float4 ra0, ra1, rb;

#define STORE_TILE(b) do {                                                     \
    As[b][kq+0][lrow]    = ra0.x; As[b][kq+1][lrow]    = ra0.y;                \
    As[b][kq+2][lrow]    = ra0.z; As[b][kq+3][lrow]    = ra0.w;                \
    As[b][kq+0][lrow+64] = ra1.x; As[b][kq+1][lrow+64] = ra1.y;                \
    As[b][kq+2][lrow+64] = ra1.z; As[b][kq+3][lrow+64] = ra1.w;                \
    Bs[b][kq+0][lrow]    = rb.x;  Bs[b][kq+1][lrow]    = rb.y;                 \
    Bs[b][kq+2][lrow]    = rb.z;  Bs[b][kq+3][lrow]    = rb.w;                 \
} while (0)

#define COMP_TILE(b) do {                                                      \
    _Pragma("unroll")                                                          \
    for (int kk = 0; kk < BK; kk++) {                                          \
        const float* Ak = &As[b][kk][ty * 8];                                  \
        ull a01 = *(const ull*)(Ak + 0), a23 = *(const ull*)(Ak + 2);          \
        ull a45 = *(const ull*)(Ak + 4), a67 = *(const ull*)(Ak + 6);          \
        float4 bv = *(const float4*)&Bs[b][kk][tx * 4];                        \
        ull b0 = pack2f(bv.x, bv.x), b1 = pack2f(bv.y, bv.y);                  \
        ull b2 = pack2f(bv.z, bv.z), b3 = pack2f(bv.w, bv.w);                  \
        ffma2(acc[0][0], a01, b0); ffma2(acc[0][1], a01, b1);                  \
        ffma2(acc[0][2], a01, b2); ffma2(acc[0][3], a01, b3);                  \
        ffma2(acc[1][0], a23, b0); ffma2(acc[1][1], a23, b1);                  \
        ffma2(acc[1][2], a23, b2); ffma2(acc[1][3], a23, b3);                  \
        ffma2(acc[2][0], a45, b0); ffma2(acc[2][1], a45, b1);                  \
        ffma2(acc[2][2], a45, b2); ffma2(acc[2][3], a45, b3);                  \
        ffma2(acc[3][0], a67, b0); ffma2(acc[3][1], a67, b1);                  \
        ffma2(acc[3][2], a67, b2); ffma2(acc[3][3], a67, b3);                  \
    }                                                                          \
} while (0)

    ra0 = *(const float4*)Ag0; ra1 = *(const float4*)Ag1; rb = *(const float4*)Bg;
    STORE_TILE(0);
    __syncthreads();

    for (int kt = 0; kt < NK; kt++) {
        const int buf = kt & 1;
        if (kt + 1 < NK) {
            ra0 = *(const float4*)(Ag0 + (kt + 1) * BK);
            ra1 = *(const float4*)(Ag1 + (kt + 1) * BK);
            rb  = *(const float4*)(Bg  + (kt + 1) * BK);
        }
        COMP_TILE(buf);
        if (kt + 1 < NK) {
            STORE_TILE(buf ^ 1);
            __syncthreads();
        }
    }

    if (MODE == 0) {
        const int t = bn >> 9;          // 0=q, 1=k, 2=v   (BN == DH == 64)
        const int h = (bn >> 6) & 7;
        #pragma unroll
        for (int p = 0; p < 4; p++) {
            float lo0, hi0, lo1, hi1, lo2, hi2, lo3, hi3;
            unpack2f(acc[p][0], lo0, hi0); unpack2f(acc[p][1], lo1, hi1);
            unpack2f(acc[p][2], lo2, hi2); unpack2f(acc[p][3], lo3, hi3);
            const int r = bm + ty * 8 + p * 2;
            const size_t rowoff = ((size_t)h * NQ + r) * DH + tx * 4;
            if (t == 0) {
                *(float4*)(g_q + rowoff)      = make_float4(lo0, lo1, lo2, lo3);
                *(float4*)(g_q + rowoff + DH) = make_float4(hi0, hi1, hi2, hi3);
            } else if (t == 1) {
                *(float4*)(g_k + rowoff)      = make_float4(lo0, lo1, lo2, lo3);
                *(float4*)(g_k + rowoff + DH) = make_float4(hi0, hi1, hi2, hi3);
                *(uint2*)(g_kh + rowoff)      = make_uint2(pk_h2(lo0, lo1), pk_h2(lo2, lo3));
                *(uint2*)(g_kh + rowoff + DH) = make_uint2(pk_h2(hi0, hi1), pk_h2(hi2, hi3));
            } else {
                *(uint2*)(g_vh + rowoff)      = make_uint2(pk_h2(lo0, lo1), pk_h2(lo2, lo3));
                *(uint2*)(g_vh + rowoff + DH) = make_uint2(pk_h2(hi0, hi1), pk_h2(hi2, hi3));
            }
        }
    } else {
        float4 bv = *(const float4*)(bias + bn + tx * 4);
        #pragma unroll
        for (int p = 0; p < 4; p++) {
            float lo0, hi0, lo1, hi1, lo2, hi2, lo3, hi3;
            unpack2f(acc[p][0], lo0, hi0); unpack2f(acc[p][1], lo1, hi1);
            unpack2f(acc[p][2], lo2, hi2); unpack2f(acc[p][3], lo3, hi3);
            const int r = bm + ty * 8 + p * 2;
            float* rp = Cout + (size_t)r * CDIM + bn + tx * 4;
            *(float4*)rp = make_float4(lo0 + bv.x, lo1 + bv.y, lo2 + bv.z, lo3 + bv.w);
            *(float4*)(rp + CDIM) = make_float4(hi0 + bv.x, hi1 + bv.y, hi2 + bv.z, hi3 + bv.w);
        }
    }
#undef STORE_TILE
#undef COMP_TILE
}

// ---------------------------------------------------------------------------
// Centroids: mean of each 32-row K segment (fp32 K).
// ---------------------------------------------------------------------------
__global__ void __launch_bounds__(64) centroid_kernel()
{
    const int hm = blockIdx.x;
    const int d = threadIdx.x;
    const float* kp = g_k + (size_t)hm * SEG * DH + d;
    float s = 0.f;
    #pragma unroll
    for (int r = 0; r < SEG; r++) s += kp[r * DH];
    g_cent[(size_t)hm * DH + d] = s * (1.0f / SEG);
}

// ---------------------------------------------------------------------------
// Zero the routing counters (runs every replay — graph determinism).
// ---------------------------------------------------------------------------
__global__ void __launch_bounds__(512) zero_kernel()
{
    g_cnt[threadIdx.x] = 0;
}

// ---------------------------------------------------------------------------
// Routing v2: ONE THREAD PER QUERY. q row in registers (f32x2-packed);
// centroids staged in smem once per block and read as warp-broadcast LDS.128
// (conflict-free). Streaming in-register top-4: strict > on ascending m
// reproduces jax.lax.top_k tie-break (lower index wins).
// grid = NH * (NQ/256) = 64 blocks x 256 threads.
// ---------------------------------------------------------------------------
__global__ void __launch_bounds__(256) route_kernel()
{
    __shared__ __align__(16) float cs[NL][DH];   // 16 KB, broadcast reads only

    const int tid = threadIdx.x;
    const int h = blockIdx.x >> 3;
    const int n = (blockIdx.x & 7) * 256 + tid;

    // stage centroid table (coalesced: 1024 float4, 4 per thread)
    {
        const float4* src = (const float4*)(g_cent + (size_t)h * NL * DH);
        float4* dst = (float4*)&cs[0][0];
        #pragma unroll
        for (int i = 0; i < 4; i++) dst[tid + i * 256] = src[tid + i * 256];
    }
    __syncthreads();

    // q row -> 32 packed f32x2 registers
    ull q2[DH / 2];
    {
        const float4* qp = (const float4*)(g_q + ((size_t)h * NQ + n) * DH);
        #pragma unroll
        for (int i = 0; i < DH / 4; i++) {
            float4 v = qp[i];
            q2[2 * i]     = pack2f(v.x, v.y);
            q2[2 * i + 1] = pack2f(v.z, v.w);
        }
    }

    float tv0 = -INFINITY, tv1 = -INFINITY, tv2 = -INFINITY, tv3 = -INFINITY;
    int   ti0 = 0, ti1 = 0, ti2 = 0, ti3 = 0;

    #pragma unroll 4
    for (int m = 0; m < NL; m++) {
        ull a0 = 0ull, a1 = 0ull, a2 = 0ull, a3 = 0ull;
        const float4* cp = (const float4*)&cs[m][0];
        #pragma unroll
        for (int i = 0; i < DH / 8; i++) {            // 8 iters x 2 float4
            float4 c0 = cp[2 * i], c1 = cp[2 * i + 1];   // LDS.128 broadcast
            ffma2(a0, q2[4 * i],     pack2f(c0.x, c0.y));
            ffma2(a1, q2[4 * i + 1], pack2f(c0.z, c0.w));
            ffma2(a2, q2[4 * i + 2], pack2f(c1.x, c1.y));
            ffma2(a3, q2[4 * i + 3], pack2f(c1.z, c1.w));
        }
        float x0, y0, x1, y1, x2, y2, x3, y3;
        unpack2f(a0, x0, y0); unpack2f(a1, x1, y1);
        unpack2f(a2, x2, y2); unpack2f(a3, x3, y3);
        const float s = ((x0 + y0) + (x1 + y1)) + ((x2 + y2) + (x3 + y3));

        // streaming top-4 insert (strict >: earlier m wins ties)
        if (s > tv3) {
            if (s > tv2) {
                tv3 = tv2; ti3 = ti2;
                if (s > tv1) {
                    tv2 = tv1; ti2 = ti1;
                    if (s > tv0) { tv1 = tv0; ti1 = ti0; tv0 = s; ti0 = m; }
                    else         { tv1 = s; ti1 = m; }
                } else { tv2 = s; ti2 = m; }
            } else { tv3 = s; ti3 = m; }
        }
    }

    // append (n, rank) to each selected landmark's list
    int slot;
    slot = atomicAdd(&g_cnt[h * NL + ti0], 1);
    g_list[(size_t)(h * NL + ti0) * NQ + slot] = n;
    slot = atomicAdd(&g_cnt[h * NL + ti1], 1);
    g_list[(size_t)(h * NL + ti1) * NQ + slot] = n | (1 << 16);
    slot = atomicAdd(&g_cnt[h * NL + ti2], 1);
    g_list[(size_t)(h * NL + ti2) * NQ + slot] = n | (2 << 16);
    slot = atomicAdd(&g_cnt[h * NL + ti3], 1);
    g_list[(size_t)(h * NL + ti3) * NQ + slot] = n | (3 << 16);
}

// ---------------------------------------------------------------------------
// Phase A: one block per (h, landmark). K/V segment staged in smem once;
// each warp holds key row `lane` in registers and streams routed queries,
// writing flash-style partials (m, l, o[64]) indexed by (h, n, rank).
// ---------------------------------------------------------------------------
__global__ void __launch_bounds__(256) seg_attn_kernel()
{
    __shared__ __half ks[SEG][DH + 2];   // +2 halves: 132B row stride (bank-safe)
    __shared__ __half2 vs[SEG][DH / 2];  // natural layout: conflict-free by lane
    __shared__ float sq[8][64];
    __shared__ float sp[8][SEG];
    __shared__ int s_cnt;

    const int tid = threadIdx.x, warp = tid >> 5, lane = tid & 31;
    const int hm = blockIdx.x;           // h*NL + m
    const int h = hm >> 6;
    const float scale = 0.125f;

    const size_t seg_base = (size_t)hm * SEG * DH;   // == (h*NQ + m*SEG)*DH
    for (int i = tid; i < SEG * DH; i += 256) {
        int r = i >> 6, c = i & 63;
        ks[r][c] = g_kh[seg_base + i];
        ((__half*)&vs[r][0])[c] = g_vh[seg_base + i];
    }
    if (tid == 0) s_cnt = g_cnt[hm];
    __syncthreads();

    __half2 kreg[DH / 2];
    #pragma unroll
    for (int c = 0; c < DH / 2; c++)
        kreg[c] = *(const __half2*)&ks[lane][2 * c];

    const int cnt = s_cnt;
    const int* list = g_list + (size_t)hm * NQ;

    for (int i = warp; i < cnt; i += 8) {
        const int e = list[i];
        const int n = e & 0xffff, t = e >> 16;

        const float* qp = g_q + ((size_t)h * NQ + n) * DH;
        sq[warp][lane] = qp[lane];
        sq[warp][lane + 32] = qp[lane + 32];
        __syncwarp();

        float s = 0.f;
        #pragma unroll
        for (int c = 0; c < DH / 2; c++) {
            float2 kf = __half22float2(kreg[c]);
            s += sq[warp][2 * c] * kf.x + sq[warp][2 * c + 1] * kf.y;
        }
        s *= scale;

        float mx = s;
        #pragma unroll
        for (int o = 16; o; o >>= 1) mx = fmaxf(mx, __shfl_xor_sync(0xffffffffu, mx, o));
        float p = __expf(s - mx);
        float l = p;
        #pragma unroll
        for (int o = 16; o; o >>= 1) l += __shfl_xor_sync(0xffffffffu, l, o);

        sp[warp][lane] = p;
        __syncwarp();

        float ax = 0.f, ay = 0.f;
        #pragma unroll
        for (int j = 0; j < SEG; j++) {
            float pj = sp[warp][j];
            float2 v = __half22float2(vs[j][lane]);
            ax += pj * v.x; ay += pj * v.y;
        }

        const size_t pb = ((size_t)h * NQ + n) * KL + t;
        *(float2*)(g_po + pb * DH + 2 * lane) = make_float2(ax, ay);
        if (lane == 0) { g_pm[pb] = mx; g_pl[pb] = l; }
        __syncwarp();
    }
}

// ---------------------------------------------------------------------------
// Combine: merge the 4 rank partials per query (exact two-level softmax).
// ---------------------------------------------------------------------------
__global__ void __launch_bounds__(256) combine_kernel()
{
    const int warp = threadIdx.x >> 5, lane = threadIdx.x & 31;
    const int gw = blockIdx.x * 8 + warp;
    const int h = gw >> 11;
    const int n = gw & (NQ - 1);

    const size_t pb = ((size_t)h * NQ + n) * KL;

    float m0 = g_pm[pb + 0], m1 = g_pm[pb + 1], m2 = g_pm[pb + 2], m3 = g_pm[pb + 3];
    float l0 = g_pl[pb + 0], l1 = g_pl[pb + 1], l2 = g_pl[pb + 2], l3 = g_pl[pb + 3];
    const float M = fmaxf(fmaxf(m0, m1), fmaxf(m2, m3));
    const float w0 = __expf(m0 - M), w1 = __expf(m1 - M);
    const float w2 = __expf(m2 - M), w3 = __expf(m3 - M);
    const float inv = 1.0f / (l0 * w0 + l1 * w1 + l2 * w2 + l3 * w3);

    float2 o0 = *(const float2*)(g_po + (pb + 0) * DH + 2 * lane);
    float2 o1 = *(const float2*)(g_po + (pb + 1) * DH + 2 * lane);
    float2 o2 = *(const float2*)(g_po + (pb + 2) * DH + 2 * lane);
    float2 o3 = *(const float2*)(g_po + (pb + 3) * DH + 2 * lane);

    float ax = w0 * o0.x + w1 * o1.x + w2 * o2.x + w3 * o3.x;
    float ay = w0 * o0.y + w1 * o1.y + w2 * o2.y + w3 * o3.y;

    float* op = g_attn + (size_t)n * CDIM + h * DH + 2 * lane;
    *(float2*)op = make_float2(ax * inv, ay * inv);
}

// ---------------------------------------------------------------------------
extern "C" void kernel_launch(void* const* d_in, const int* in_sizes, int n_in,
                              void* d_out, int out_size)
{
    const float* x      = (const float*)d_in[0];   // (1, 2048, 512)
    const float* w_qkv  = (const float*)d_in[1];   // (1536, 512)
    const float* w_proj = (const float*)d_in[2];   // (512, 512)
    const float* b_proj = (const float*)d_in[3];   // (512,)
    float* out = (float*)d_out;                    // (1, 2048, 512)

    // 1) QKV GEMM (f32x2) + scatter q/k fp32, k/v fp16
    gemm_kernel<0><<<dim3(3 * CDIM / 64, NQ / 128), 256>>>(x, w_qkv, nullptr, nullptr);
    // 2) Landmark centroids (fp32)
    centroid_kernel<<<NH * NL, 64>>>();
    // 3) Routing v2: lane-per-query streaming top-4 + inverted lists
    zero_kernel<<<1, 512>>>();
    route_kernel<<<NH * NQ / 256, 256>>>();
    // 4) Phase A: per-(h,landmark) segment attention -> partials
    seg_attn_kernel<<<NH * NL, 256>>>();
    // 5) Combine partials (exact softmax merge)
    combine_kernel<<<NH * NQ / 8, 256>>>();
    // 6) Output projection + bias (f32x2)
    gemm_kernel<1><<<dim3(CDIM / 64, NQ / 128), 256>>>(nullptr, w_proj, b_proj, out);
}